// round 11
// baseline (speedup 1.0000x reference)
#include <cuda_runtime.h>
#include <math.h>
#include <stdint.h>

// Problem constants
#define T_DIM 2048
#define B_DIM 1024
#define A_DIM 4
#define D_DIM 128

constexpr int THREADS = 256;
constexpr int CHUNK   = 32;               // timesteps per tile -> 128 GEMM rows
constexpr int NCHUNK  = T_DIM / CHUNK;    // 64
constexpr int SROW    = 136;              // padded row stride: 8-bank offset per row

// Output layout: [logits (T,1,B,A)] [q (B,A,D)] [h (B,A,D)]
constexpr int OUT_Q = T_DIM * B_DIM * A_DIM;
constexpr int OUT_H = OUT_Q + B_DIM * A_DIM * D_DIM;

// SMEM layout (float offsets)
constexpr int SM_B      = 0;                    // C^T tf32 (logical cols): sB[e*SROW + d]
constexpr int SM_A      = SM_B + 128 * SROW;    // H tile, PAIR-PERMUTED cols, tf32 bits
constexpr int SM_Q      = SM_A + 128 * SROW;    // Q tile, logical cols, fp32
constexpr int SM_PHI    = SM_Q + 128 * SROW;
constexpr int SM_OMPHI  = SM_PHI + 128;
constexpr int SM_CHI    = SM_OMPHI + 128;
constexpr int SM_OMCHI  = SM_CHI + 128;
constexpr int SM_BETA   = SM_OMCHI + 128;       // logical order (epilogue)
constexpr int SM_KAPPAP = SM_BETA + 128;        // PAIR-PERMUTED order (kappa.h)
constexpr int SM_INP    = SM_KAPPAP + 128;      // 32 t x 8
constexpr int SM_PART   = SM_INP + 256;         // 4 col-groups x 128 rows
constexpr int SM_KH     = SM_PART + 512;        // 128
constexpr int SM_TOT    = SM_KH + 128;          // 53888 floats
constexpr int SMEM_BYTES = SM_TOT * 4;          // 215,552 B

// pair permutation: logical col c -> slot (c&~7) + ( (c&7)<4 ? 2*(c&7) : 2*((c&7)-4)+1 )
__device__ __host__ __forceinline__ int pslot(int c) {
    int l = c & 7;
    return (c & ~7) + ((l < 4) ? (l << 1) : (((l - 4) << 1) | 1));
}

__device__ __forceinline__ uint32_t f2tf(float x) {
    uint32_t u;
    asm("cvt.rna.tf32.f32 %0, %1;" : "=r"(u) : "f"(x));
    return u;
}

__device__ __forceinline__ void mma_tf32(float* c, const uint32_t* a, const uint32_t* b) {
    asm volatile(
        "mma.sync.aligned.m16n8k8.row.col.f32.tf32.tf32.f32 "
        "{%0,%1,%2,%3}, {%4,%5,%6,%7}, {%8,%9}, {%0,%1,%2,%3};\n"
        : "+f"(c[0]), "+f"(c[1]), "+f"(c[2]), "+f"(c[3])
        : "r"(a[0]), "r"(a[1]), "r"(a[2]), "r"(a[3]),
          "r"(b[0]), "r"(b[1]));
}

__global__ __launch_bounds__(THREADS, 1)
void gql_kernel(const float* __restrict__ inp,       // (T,1,B,9)
                const float* __restrict__ phi_raw,   // (P,D)
                const float* __restrict__ chi_raw,
                const float* __restrict__ beta_raw,
                const float* __restrict__ kap_raw,
                const float* __restrict__ C_raw,     // (P,D,D)
                float* __restrict__ out)
{
    extern __shared__ float sm[];
    const int b    = blockIdx.x;
    const int tid  = threadIdx.x;
    const int lane = tid & 31;
    const int warp = tid >> 5;

    const int pid = (int)inp[b * 9 + 8];

    // ---------------- one-time parameter setup ----------------
    if (tid < 128) {
        const int d = tid;
        float pv = phi_raw[pid * 128 + d];
        float ph = 1.0f / (1.0f + expf(-pv));
        ph = fminf(fmaxf(ph, 0.01f), 0.99f);
        sm[SM_PHI + d]   = ph;
        sm[SM_OMPHI + d] = 1.0f - ph;

        float cv = chi_raw[pid * 128 + d];
        float ch = 1.0f / (1.0f + expf(-cv));
        ch = fminf(fmaxf(ch, 0.01f), 0.99f);
        sm[SM_CHI + d]   = ch;
        sm[SM_OMCHI + d] = 1.0f - ch;

        float bv = beta_raw[pid * 128 + d];
        float sp = (bv > 15.0f) ? bv : log1pf(expf(bv));
        sm[SM_BETA + d] = fminf(fmaxf(sp, 0.1f), 10.0f);

        float kv = kap_raw[pid * 128 + d];
        sm[SM_KAPPAP + pslot(d)] = fminf(fmaxf(kv, -10.0f), 10.0f);
    }

    // C[pid]: clip, tf32-round, store transposed (logical cols)
    {
        const float* Cb = C_raw + (size_t)pid * (128 * 128);
        for (int i = tid; i < 128 * 128; i += THREADS) {
            int d = i >> 7, e = i & 127;
            float v = fminf(fmaxf(Cb[i], -10.0f), 10.0f);
            sm[SM_B + e * SROW + d] = __uint_as_float(f2tf(v));
        }
    }
    __syncthreads();

    // warp tile: 64 rows x 32 cols. wm in {0,1}, wn in {0..3}
    const int wm  = warp >> 2;
    const int wn  = warp & 3;
    const int grp = lane >> 2;   // 0..7
    const int qd  = lane & 3;    // 0..3

    // ---- hoist B fragments (C^T) into registers: invariant across chunks ----
    uint32_t bf[16][4][2];
#pragma unroll
    for (int k = 0; k < 16; k++) {
#pragma unroll
        for (int j = 0; j < 4; j++) {
            const float* base = &sm[SM_B + (wn * 32 + j * 8 + grp) * SROW + k * 8 + qd];
            bf[k][j][0] = __float_as_uint(base[0]);
            bf[k][j][1] = __float_as_uint(base[4]);
        }
    }

    // ---------------- per-thread scan state: owns logical dims (c0, c0+4) ----
    const int u     = tid & 63;
    const int a_own = tid >> 6;
    const int g8    = u >> 2;
    const int s4    = u & 3;
    const int c0    = g8 * 8 + s4;     // logical col
    const int c1    = c0 + 4;
    const int slot0 = g8 * 8 + 2 * s4; // permuted slot of (c0, c1) pair

    const float phi0 = sm[SM_PHI + c0],   phi1 = sm[SM_PHI + c1];
    const float omp0 = sm[SM_OMPHI + c0], omp1 = sm[SM_OMPHI + c1];
    const float chi0 = sm[SM_CHI + c0],   chi1 = sm[SM_CHI + c1];
    const float omc0 = sm[SM_OMCHI + c0], omc1 = sm[SM_OMCHI + c1];

    float q0 = 0.5f, q1 = 0.5f, h0 = 0.0f, h1 = 0.0f;

    for (int c = 0; c < NCHUNK; c++) {
        const int tb = c * CHUNK;

        // ---- stage 1: load chunk inputs ----
        {
            int t = tid >> 3, cc = tid & 7;
            float v = inp[((size_t)(tb + t) * B_DIM + b) * 9 + cc];
            if (v != v) v = 0.0f;   // nan_to_num
            sm[SM_INP + tid] = v;
        }
        __syncthreads();

        // ---- stage 2: EMA scan -> H (tf32, permuted pairs) + Q (fp32, logical) ----
#pragma unroll 8
        for (int t = 0; t < CHUNK; t++) {
            float av = sm[SM_INP + t * 8 + a_own];
            float rv = sm[SM_INP + t * 8 + 4 + a_own];
            float drive = rv * av;
            q0 = fmaf(phi0, drive, omp0 * q0);
            q1 = fmaf(phi1, drive, omp1 * q1);
            h0 = fmaf(chi0, av, omc0 * h0);
            h1 = fmaf(chi1, av, omc1 * h1);
            int row = t * 4 + a_own;
            *(float2*)&sm[SM_A + row * SROW + slot0] =
                make_float2(__uint_as_float(f2tf(h0)), __uint_as_float(f2tf(h1)));
            sm[SM_Q + row * SROW + c0] = q0;
            sm[SM_Q + row * SROW + c1] = q1;
        }
        __syncthreads();

        // ---- stage 3: P = H * C (tf32 mma), warp tile 64x32, LDS.64 A frags ----
        float acc[4][4][4];
#pragma unroll
        for (int i = 0; i < 4; i++)
#pragma unroll
            for (int j = 0; j < 4; j++)
#pragma unroll
                for (int r = 0; r < 4; r++) acc[i][j][r] = 0.0f;

#pragma unroll
        for (int k = 0; k < 16; k++) {
            uint32_t af[4][4];
#pragma unroll
            for (int i = 0; i < 4; i++) {
                const int r0 = wm * 64 + i * 16 + grp;
                float2 v0 = *(const float2*)&sm[SM_A + r0 * SROW + k * 8 + qd * 2];
                float2 v1 = *(const float2*)&sm[SM_A + (r0 + 8) * SROW + k * 8 + qd * 2];
                af[i][0] = __float_as_uint(v0.x);   // (grp,   k*8+qd)
                af[i][1] = __float_as_uint(v1.x);   // (grp+8, k*8+qd)
                af[i][2] = __float_as_uint(v0.y);   // (grp,   k*8+qd+4)
                af[i][3] = __float_as_uint(v1.y);   // (grp+8, k*8+qd+4)
            }
#pragma unroll
            for (int i = 0; i < 4; i++)
#pragma unroll
                for (int j = 0; j < 4; j++)
                    mma_tf32(acc[i][j], af[i], bf[k][j]);
        }

        // ---- kappa . h (permuted order; dot is order-invariant) ----
        {
            int row = tid >> 1, half = tid & 1;
            float kh = 0.0f;
            const float4* hv = (const float4*)&sm[SM_A + row * SROW + half * 64];
            const float4* kv = (const float4*)&sm[SM_KAPPAP + half * 64];
#pragma unroll
            for (int d = 0; d < 16; d++) {
                float4 hh = hv[d], kk = kv[d];
                kh += hh.x * kk.x + hh.y * kk.y + hh.z * kk.z + hh.w * kk.w;
            }
            kh += __shfl_xor_sync(0xFFFFFFFFu, kh, 1);
            if (half == 0) sm[SM_KH + row] = kh;
        }

        // ---- epilogue: rowdot((P + beta^T), Q) -> PART[wn][row] ----
#pragma unroll
        for (int i = 0; i < 4; i++) {
            float part0 = 0.0f, part1 = 0.0f;
            const int r0 = wm * 64 + i * 16 + grp;
            const int r1 = r0 + 8;
#pragma unroll
            for (int j = 0; j < 4; j++) {
                const int col = wn * 32 + j * 8 + qd * 2;
                const float b0 = sm[SM_BETA + col];
                const float b1 = sm[SM_BETA + col + 1];
                float2 qv0 = *(const float2*)&sm[SM_Q + r0 * SROW + col];
                float2 qv1 = *(const float2*)&sm[SM_Q + r1 * SROW + col];
                part0 += (acc[i][j][0] + b0) * qv0.x + (acc[i][j][1] + b1) * qv0.y;
                part1 += (acc[i][j][2] + b0) * qv1.x + (acc[i][j][3] + b1) * qv1.y;
            }
            part0 += __shfl_xor_sync(0xFFFFFFFFu, part0, 1);
            part0 += __shfl_xor_sync(0xFFFFFFFFu, part0, 2);
            part1 += __shfl_xor_sync(0xFFFFFFFFu, part1, 1);
            part1 += __shfl_xor_sync(0xFFFFFFFFu, part1, 2);
            if (qd == 0) {
                sm[SM_PART + wn * 128 + r0] = part0;
                sm[SM_PART + wn * 128 + r1] = part1;
            }
        }
        __syncthreads();

        // ---- stage 5: combine col-groups + kappa.h, write logits (T,1,B,A) ----
        if (tid < 128) {
            float l = sm[SM_PART + tid] + sm[SM_PART + 128 + tid]
                    + sm[SM_PART + 256 + tid] + sm[SM_PART + 384 + tid]
                    + sm[SM_KH + tid];
            int t = tb + (tid >> 2);
            int a = tid & 3;
            out[(size_t)t * (B_DIM * A_DIM) + b * A_DIM + a] = l;
        }
        __syncthreads();
    }

    // ---- final states: q (B,A,D) then h (B,A,D); logical (a,d) indices ----
    out[OUT_Q + (size_t)b * 512 + a_own * 128 + c0] = q0;
    out[OUT_Q + (size_t)b * 512 + a_own * 128 + c1] = q1;
    out[OUT_H + (size_t)b * 512 + a_own * 128 + c0] = h0;
    out[OUT_H + (size_t)b * 512 + a_own * 128 + c1] = h1;
}

extern "C" void kernel_launch(void* const* d_in, const int* in_sizes, int n_in,
                              void* d_out, int out_size) {
    const float* inp      = (const float*)d_in[0];
    const float* phi_raw  = (const float*)d_in[1];
    const float* chi_raw  = (const float*)d_in[2];
    const float* beta_raw = (const float*)d_in[3];
    const float* kap_raw  = (const float*)d_in[4];
    const float* C_raw    = (const float*)d_in[5];
    float* out = (float*)d_out;

    cudaFuncSetAttribute(gql_kernel, cudaFuncAttributeMaxDynamicSharedMemorySize, SMEM_BYTES);
    gql_kernel<<<B_DIM, THREADS, SMEM_BYTES>>>(inp, phi_raw, chi_raw, beta_raw,
                                               kap_raw, C_raw, out);
}